// round 16
// baseline (speedup 1.0000x reference)
#include <cuda_runtime.h>

// SegGPS_66949950210076
// out[b] = sum_m prod_l eps[idx[b,l], m, l, nup[b,l], ndn[b,l]]
// B=8192, L=64, M=64, LOCAL_DIM=4, eps (4,64,64,65,65) fp32.
//
// R12: 3 kernels.
//  K1 prep: CTAs 0-255 compute per-l (nup,ndn) bounding boxes (4 batches/warp,
//     hoisted loads, atomicMin into 4 SHADOW copies -> 64-deep queues);
//     CTAs 256-391 concurrently transpose ALL l<16 rows (box ~= full there).
//  K2 box transpose for l>=16 into T[cell][idx][m] (256B m-contiguous).
//  K3 gather (warp/batch, float4 lane-split); restores bound sentinels.

#define B_SZ   8192
#define L_SZ   64
#define IDX_STRIDE 17305600   // M*L*65*65
#define M_STRIDE   270400     // L*65*65
#define L_STRIDE   4225       // 65*65
#define CELLS  89440          // sum_{k=1..64} k^2
#define T_ELEMS (CELLS * 256)
#define SMALL_L 16
#define SMALL_ROWS 136        // sum_{l<16}(l+1)

__device__ __align__(256) float g_T[T_ELEMS];  // 91.6 MB scratch (static)

// 4 shadow copies, each field-major [field][l]. Shadow stride 1KB -> distinct
// L2 lines; fields within a shadow on separate 128B lines.
// fields: 0=min nup, 1=64-max nup, 2=min ndn, 3=64-max ndn. Sentinel=64.
#define S8  64u,64u,64u,64u,64u,64u,64u,64u
#define S64 {S8,S8,S8,S8,S8,S8,S8,S8}
__device__ unsigned g_bounds4[4][4][L_SZ] = {
    {S64, S64, S64, S64}, {S64, S64, S64, S64},
    {S64, S64, S64, S64}, {S64, S64, S64, S64} };

__device__ __forceinline__ int cell_off(int l) {
    return l * (l + 1) * (2 * l + 1) / 6;      // sum_{j=1..l} j^2
}
__device__ __forceinline__ float4 mul4(float4 a, float4 b) {
    return make_float4(a.x * b.x, a.y * b.y, a.z * b.z, a.w * b.w);
}
__device__ __forceinline__ unsigned min4u(unsigned a, unsigned b,
                                          unsigned c, unsigned d) {
    unsigned x = a < b ? a : b, y = c < d ? c : d;
    return x < y ? x : y;
}

// Per-warp dtype probe. Indices are logically int64 (ref) but JAX x64-off
// emits int32. Under int64 LE every odd 32-bit word is 0 (values < 4); under
// int32 odd words are random in [0,4). Probe 64 odd words of a fixed
// 128-word window within the first 524288 words (in-bounds either way).
// P(false int64 | int32) = 0.25^64 per warp.
__device__ __forceinline__ int probe_is_int32(const unsigned* __restrict__ w,
                                              int b, int lane) {
    int base = (b & 4095) * 128;
    unsigned x = w[base + 2 * lane + 1] | w[base + 64 + 2 * lane + 1];
    return __ballot_sync(0xffffffffu, x != 0u) != 0u;
}

__device__ __forceinline__ void scan_vals(
    int v0, int v1, int lane,
    int& nup0, int& ndn0, int& nup1, int& ndn1)
{
    unsigned bu0 = __ballot_sync(0xffffffffu, v0 & 1);
    unsigned bd0 = __ballot_sync(0xffffffffu, v0 & 2);
    unsigned bu1 = __ballot_sync(0xffffffffu, v1 & 1);
    unsigned bd1 = __ballot_sync(0xffffffffu, v1 & 2);
    unsigned mlt = (1u << lane) - 1u;
    nup0 = __popc(bu0 & mlt);               ndn0 = __popc(bd0 & mlt);
    nup1 = __popc(bu0) + __popc(bu1 & mlt); ndn1 = __popc(bd0) + __popc(bd1 & mlt);
}

__device__ __forceinline__ void load_batch(
    const void* idx_raw, int is32, int b, int lane, int& v0, int& v1)
{
    if (is32) {
        const int* p = (const int*)idx_raw + b * L_SZ;
        v0 = p[lane];  v1 = p[lane + 32];
    } else {
        const long long* p = (const long long*)idx_raw + (size_t)b * L_SZ;
        v0 = (int)p[lane];  v1 = (int)p[lane + 32];
    }
}

// ---- K1: bounds (CTA 0..255) + small-l transpose (CTA 256..391) ----
__global__ __launch_bounds__(256) void prep_kernel(
    const void* __restrict__ idx_raw, const float* __restrict__ eps)
{
    if (blockIdx.x < 256) {
        // ===== bounds: 4 batches per warp, hoisted loads =====
        __shared__ unsigned red[8][64];
        const int lane = threadIdx.x & 31;
        const int w    = threadIdx.x >> 5;
        const int b0   = blockIdx.x * 32 + w * 4;

        int is32 = probe_is_int32((const unsigned*)idx_raw, b0, lane);

        int va[4], vb[4];
        #pragma unroll
        for (int i = 0; i < 4; i++)
            load_batch(idx_raw, is32, b0 + i, lane, va[i], vb[i]);

        unsigned acc0 = 0xFFFFFFFFu, acc1 = 0xFFFFFFFFu;
        #pragma unroll
        for (int i = 0; i < 4; i++) {
            int nu0, nd0, nu1, nd1;
            scan_vals(va[i], vb[i], lane, nu0, nd0, nu1, nd1);
            unsigned r0 = (unsigned)(nu0 | ((64 - nu0) << 8) |
                                     (nd0 << 16) | ((64 - nd0) << 24));
            unsigned r1 = (unsigned)(nu1 | ((64 - nu1) << 8) |
                                     (nd1 << 16) | ((64 - nd1) << 24));
            acc0 = __vminu4(acc0, r0);
            acc1 = __vminu4(acc1, r1);
        }
        red[w][lane]      = acc0;
        red[w][lane + 32] = acc1;
        __syncthreads();

        if (threadIdx.x < 64) {
            const int l = threadIdx.x;
            const int s = blockIdx.x & 3;           // shadow copy
            unsigned r = red[0][l];
            #pragma unroll
            for (int k = 1; k < 8; k++) r = __vminu4(r, red[k][l]);
            atomicMin(&g_bounds4[s][0][l],  r        & 255u);
            atomicMin(&g_bounds4[s][1][l], (r >>  8) & 255u);
            atomicMin(&g_bounds4[s][2][l], (r >> 16) & 255u);
            atomicMin(&g_bounds4[s][3][l],  r >> 24        );
        }
    } else {
        // ===== small-l transpose: row r -> (l, nup), full triangle =====
        int r = blockIdx.x - 256;                   // 0..135
        int l = 0;
        while ((l + 1) * (l + 2) / 2 <= r) l++;     // l < 16
        const int nup = r - l * (l + 1) / 2;
        const int nv = l + 1;                       // <= 16
        const int cellbase = cell_off(l) + nup * nv;

        __shared__ float sm[64][17];
        const int tid = threadIdx.x;
        const int c16 = tid & 15;
        const int r16 = tid >> 4;                   // m sub-block 0..15
        const int cm  = tid & 63;
        const int rr  = tid >> 6;

        for (int idx = 0; idx < 4; idx++) {
            const float* src = eps + idx * IDX_STRIDE + l * L_STRIDE + nup * 65;
            if (c16 < nv) {
                #pragma unroll
                for (int mb = 0; mb < 64; mb += 16)
                    sm[mb + r16][c16] = src[(mb + r16) * M_STRIDE + c16];
            }
            __syncthreads();
            float* dst = g_T + (size_t)cellbase * 256 + idx * 64;
            #pragma unroll
            for (int nb = 0; nb < 16; nb += 4) {
                int ndn = nb + rr;
                if (ndn < nv)
                    dst[ndn * 256 + cm] = sm[cm][ndn];
            }
            __syncthreads();
        }
    }
}

// ---- K2: box transpose for l >= 16; CTA per (l, nup, idx) ----
__global__ __launch_bounds__(256) void transpose_kernel(const float* __restrict__ eps) {
    const int l = SMALL_L + blockIdx.x, nup = blockIdx.y, idx = blockIdx.z;
    if (nup > l) return;

    const int amin = (int)min4u(g_bounds4[0][0][l], g_bounds4[1][0][l],
                                g_bounds4[2][0][l], g_bounds4[3][0][l]);
    const int amax = 64 - (int)min4u(g_bounds4[0][1][l], g_bounds4[1][1][l],
                                     g_bounds4[2][1][l], g_bounds4[3][1][l]);
    if (nup < amin || nup > amax) return;
    const int cmin = (int)min4u(g_bounds4[0][2][l], g_bounds4[1][2][l],
                                g_bounds4[2][2][l], g_bounds4[3][2][l]);
    int cmax = 64 - (int)min4u(g_bounds4[0][3][l], g_bounds4[1][3][l],
                               g_bounds4[2][3][l], g_bounds4[3][3][l]);
    if (cmax > l) cmax = l;
    const int W = cmax - cmin + 1;
    if (W <= 0) return;

    const int nv = l + 1;
    const int cellbase = cell_off(l) + nup * nv;

    __shared__ float sm[64][65];

    const int tid = threadIdx.x;
    const int c64 = tid & 63;
    const int r4  = tid >> 6;

    const float* src = eps + idx * IDX_STRIDE + l * L_STRIDE + nup * 65 + cmin;
    if (c64 < W) {
        #pragma unroll
        for (int mb = 0; mb < 64; mb += 4) {
            int m = mb + r4;
            sm[m][c64] = src[m * M_STRIDE + c64];
        }
    }
    __syncthreads();

    float* dst = g_T + (size_t)cellbase * 256 + idx * 64;
    for (int nb = 0; nb < W; nb += 4) {
        int k = nb + r4;
        if (k < W)
            dst[(cmin + k) * 256 + c64] = sm[c64][k];
    }
}

// ---- K3: gather, warp per batch; restores bound sentinels ----
__global__ __launch_bounds__(256) void seggps_kernel(
    const void* __restrict__ idx_raw,
    float*      __restrict__ out)
{
    __shared__ int soffs[8][64];

    // restore atomicMin identity (transpose already consumed bounds).
    if (blockIdx.x < 4)
        ((unsigned*)g_bounds4)[blockIdx.x * 256 + threadIdx.x] = 64u;

    const int lane = threadIdx.x & 31;
    const int w    = threadIdx.x >> 5;
    const int b    = blockIdx.x * 8 + w;

    int is32 = probe_is_int32((const unsigned*)idx_raw, b, lane);
    int v0, v1, nu0, nd0, nu1, nd1;
    load_batch(idx_raw, is32, b, lane, v0, v1);
    scan_vals(v0, v1, lane, nu0, nd0, nu1, nd1);
    int c0 = cell_off(lane)      + nu0 * (lane + 1)  + nd0;
    int c1 = cell_off(lane + 32) + nu1 * (lane + 33) + nd1;
    soffs[w][lane]      = c0 * 256 + v0 * 64;
    soffs[w][lane + 32] = c1 * 256 + v1 * 64;
    __syncwarp();

    const int half = lane >> 4;             // 0: even sites, 1: odd sites
    const int q    = lane & 15;             // m-quad (4 floats)

    float4 a0 = make_float4(1.f, 1.f, 1.f, 1.f), a1 = a0, a2 = a0, a3 = a0;
    #pragma unroll
    for (int i = 0; i < 32; i += 4) {
        float4 x0 = __ldg((const float4*)(g_T + soffs[w][2 * (i + 0) + half]) + q);
        float4 x1 = __ldg((const float4*)(g_T + soffs[w][2 * (i + 1) + half]) + q);
        float4 x2 = __ldg((const float4*)(g_T + soffs[w][2 * (i + 2) + half]) + q);
        float4 x3 = __ldg((const float4*)(g_T + soffs[w][2 * (i + 3) + half]) + q);
        a0 = mul4(a0, x0);
        a1 = mul4(a1, x1);
        a2 = mul4(a2, x2);
        a3 = mul4(a3, x3);
    }
    float4 p = mul4(mul4(a0, a1), mul4(a2, a3));

    float4 o;
    o.x = __shfl_xor_sync(0xffffffffu, p.x, 16);
    o.y = __shfl_xor_sync(0xffffffffu, p.y, 16);
    o.z = __shfl_xor_sync(0xffffffffu, p.z, 16);
    o.w = __shfl_xor_sync(0xffffffffu, p.w, 16);
    p = mul4(p, o);

    float s = (p.x + p.y) + (p.z + p.w);
    #pragma unroll
    for (int off = 8; off; off >>= 1) s += __shfl_xor_sync(0xffffffffu, s, off);
    if (lane == 0) out[b] = s;
}

extern "C" void kernel_launch(void* const* d_in, const int* in_sizes, int n_in,
                              void* d_out, int out_size)
{
    const void*  idx = d_in[0];                 // indices (B,L) int32 or int64
    const float* eps = (const float*)d_in[1];   // epsilon fp32
    float* out = (float*)d_out;
    (void)in_sizes; (void)n_in; (void)out_size;

    prep_kernel<<<256 + SMALL_ROWS, 256>>>(idx, eps);
    transpose_kernel<<<dim3(64 - SMALL_L, 64, 4), 256>>>(eps);
    seggps_kernel<<<B_SZ / 8, 256>>>(idx, out);
}